// round 12
// baseline (speedup 1.0000x reference)
#include <cuda_runtime.h>

#define H 128
#define W 128
#define NCONV 8
#define TILE_ROWS 8
#define FROWS 10          // TILE_ROWS + 2 halo
#define FSTRIDE 132       // floats per (f,row) (130 used, padded)
#define F2STRIDE 66       // float2 per (f,row)
#define NTHREADS 256
#define NWARP 8
#define NTASK (FROWS * 5) // 50 feature tasks (32-wide chunks)

// dynamic smem layout (bytes)
#define OFF_F    0                                   // float F[4][10][132] = 21120
#define OFF_W    21120                               // ull   w[288]        = 2304
#define OFF_B    23424                               // ull   bias[8]       = 64
#define SMEM_BYTES 23488

typedef unsigned long long ull;

__device__ __forceinline__ ull pk2(float lo, float hi) {
    ull r; asm("mov.b64 %0, {%1, %2};" : "=l"(r) : "f"(lo), "f"(hi)); return r;
}
__device__ __forceinline__ void fma2(ull &d, ull a, ull b) {
    asm("fma.rn.f32x2 %0, %1, %2, %0;" : "+l"(d) : "l"(a), "l"(b));
}
__device__ __forceinline__ float tanh_ap(float x) {
    float r; asm("tanh.approx.f32 %0, %1;" : "=f"(r) : "f"(x)); return r;
}

// features of one input value: 2 MUFU + a few fma
__device__ __forceinline__ void feats(float xv, float &s, float &t, float &t2, float &t3) {
    t = tanh_ap(xv);                               // tanh
    float th = tanh_ap(0.5f * xv);
    float sg = fmaf(0.5f, th, 0.5f);               // sigmoid(x)
    s  = xv * sg;                                  // silu
    t2 = fmaf(t + t, t, -1.f);                     // T2
    t3 = fmaf(t + t, t2, -t);                      // T3
}

__global__ void __launch_bounds__(NTHREADS, 4)
kan_conv_kernel(const float* __restrict__ x,
                const float* __restrict__ cheby,
                const float* __restrict__ bw,
                const float* __restrict__ ss,
                float* __restrict__ out)
{
    extern __shared__ char smem_raw[];
    float* Fm    = (float*)(smem_raw + OFF_F);    // [f][row][i], i = col+1 (0..129)
    ull*   wsm   = (ull*)  (smem_raw + OFF_W);    // [(tap*4+f)*8 + j] dup pairs
    ull*   biasd = (ull*)  (smem_raw + OFF_B);

    const int tid  = threadIdx.x;
    const int wid  = tid >> 5;
    const int lane = tid & 31;
    const int blk  = blockIdx.x;
    const int bc   = blk >> 4;                    // plane b*C + c (0..255)
    const int r0   = (blk & 15) * TILE_ROWS;      // tile top row

    const float* xp = x + (size_t)bc * (H * W);

    // ---- Phase B1: prefetch all feature-input LDGs (MLP up to 7 per warp) ----
    // task = wid + 8q -> (row, chunk c), 32-wide chunks; increment-only mapping.
    float xv[7];
    {
        int row = (wid >= 5) ? 1 : 0;
        int c   = wid - ((wid >= 5) ? 5 : 0);
        #pragma unroll
        for (int q = 0; q < 7; q++) {
            int gr  = r0 - 1 + row;
            int col = (c << 5) + lane - 1;         // i - 1
            xv[q] = 0.f;
            if ((wid + q * 8 < NTASK) & ((unsigned)gr < H) & ((unsigned)col < W))
                xv[q] = xp[(gr << 7) + col];       // W == 128
            row += 1; c += 3;
            if (c >= 5) { c -= 5; row += 1; }
        }
    }

    // ---- Phase A: weights -> smem (covers the in-flight LDGs above) ----
    for (int idx = tid; idx < 9 * 4 * 8; idx += NTHREADS) {
        int j   = idx & 7;
        int fi  = idx >> 3;
        int tap = fi >> 2;
        int f   = fi & 3;
        float wv;
        if (f == 0) wv = bw[j * 9 + tap];
        else        wv = cheby[(j * 9 + tap) * 4 + f] * ss[j * 9 + tap];
        wsm[idx] = pk2(wv, wv);
    }
    if (tid < NCONV) {
        float sum = 0.f;
        #pragma unroll
        for (int i = 0; i < 9; i++) sum += cheby[(tid * 9 + i) * 4] * ss[tid * 9 + i];
        biasd[tid] = pk2(sum, sum);
    }

    // ---- Phase B2: features -> scalar smem (dense STS.32, no shfl/pairing) ----
    {
        int c    = wid - ((wid >= 5) ? 5 : 0);
        int rowF = ((wid >= 5) ? 1 : 0) * FSTRIDE;
        #pragma unroll
        for (int q = 0; q < 7; q++) {
            int i = (c << 5) + lane;               // F index (col = i-1)
            if ((wid + q * 8 < NTASK) && i <= 129) {
                float s, t1, t2, t3;
                feats(xv[q], s, t1, t2, t3);       // x=0 padding -> (0,0,-1,0) ✓
                int b = rowF + i;
                Fm[(0 * FROWS) * FSTRIDE + b] = s;
                Fm[(1 * FROWS) * FSTRIDE + b] = t1;
                Fm[(2 * FROWS) * FSTRIDE + b] = t2;
                Fm[(3 * FROWS) * FSTRIDE + b] = t3;
            }
            c += 3;
            if (c >= 5) { c -= 5; rowF += 2 * FSTRIDE; } else { rowF += FSTRIDE; }
        }
    }
    __syncthreads();

    // ---- Compute: thread -> 2 output rows (ty, ty+1), cols {2L, 2L+1}, 8 j ----
    // Pairs rebuilt from scalar F: A=(F[2L],F[2L+1]), B=(F[2L+2],F[2L+3]):
    //   P[2L]=A, P[2L+1]=(A.y,B.x), P[2L+2]=B  — 2 dense LDS.64 + 1 pack.
    const int L  = tid & 63;                       // col-pair index, c0 = 2L
    const int ty = (tid >> 6) * 2;                 // local out rows ty, ty+1
    const float2* F2 = (const float2*)Fm;

    ull acc[8][2];                                 // [j][r]
    #pragma unroll
    for (int j = 0; j < 8; j++) {
        ull b = biasd[j];
        acc[j][0] = b; acc[j][1] = b;
    }

    const int tybase = ty * F2STRIDE + L;          // single IMAD; rest immediates

    #pragma unroll
    for (int f = 0; f < 4; f++) {
        ull lo[3], hi[3];
        {   // input rows ty (lo) and ty+1 (hi)
            int b0 = (f * FROWS) * F2STRIDE + tybase;
            float2 a0 = F2[b0], c0v = F2[b0 + 1];
            lo[0] = pk2(a0.x, a0.y); lo[1] = pk2(a0.y, c0v.x); lo[2] = pk2(c0v.x, c0v.y);
            float2 a1 = F2[b0 + F2STRIDE], c1v = F2[b0 + F2STRIDE + 1];
            hi[0] = pk2(a1.x, a1.y); hi[1] = pk2(a1.y, c1v.x); hi[2] = pk2(c1v.x, c1v.y);
        }
        #pragma unroll
        for (int dy = 0; dy < 3; dy++) {
            #pragma unroll
            for (int dx = 0; dx < 3; dx++) {
                const ulonglong2* wp = (const ulonglong2*)&wsm[((dy * 3 + dx) * 4 + f) * 8];
                ull f0 = lo[dx];                   // feeds out row ty
                ull f1 = hi[dx];                   // feeds out row ty+1
                {   // j 0..3
                    ulonglong2 w01 = wp[0], w23 = wp[1];
                    fma2(acc[0][0], f0, w01.x); fma2(acc[0][1], f1, w01.x);
                    fma2(acc[1][0], f0, w01.y); fma2(acc[1][1], f1, w01.y);
                    fma2(acc[2][0], f0, w23.x); fma2(acc[2][1], f1, w23.x);
                    fma2(acc[3][0], f0, w23.y); fma2(acc[3][1], f1, w23.y);
                }
                {   // j 4..7
                    ulonglong2 w45 = wp[2], w67 = wp[3];
                    fma2(acc[4][0], f0, w45.x); fma2(acc[4][1], f1, w45.x);
                    fma2(acc[5][0], f0, w45.y); fma2(acc[5][1], f1, w45.y);
                    fma2(acc[6][0], f0, w67.x); fma2(acc[6][1], f1, w67.x);
                    fma2(acc[7][0], f0, w67.y); fma2(acc[7][1], f1, w67.y);
                }
            }
            if (dy < 2) {                          // roll window: lo <- hi, load next row
                lo[0] = hi[0]; lo[1] = hi[1]; lo[2] = hi[2];
                int bn = (f * FROWS + dy + 2) * F2STRIDE + tybase;
                float2 an = F2[bn], cn = F2[bn + 1];
                hi[0] = pk2(an.x, an.y); hi[1] = pk2(an.y, cn.x); hi[2] = pk2(cn.x, cn.y);
            }
        }
    }

    // ---- stores: STG.64, dense per warp ----
    float* ob = out + ((size_t)(bc * NCONV) * H + (r0 + ty)) * W + 2 * L;
    #pragma unroll
    for (int j = 0; j < 8; j++) {
        #pragma unroll
        for (int r = 0; r < 2; r++) {
            *(ull*)(ob + (size_t)j * (H * W) + r * W) = acc[j][r];
        }
    }
}

extern "C" void kernel_launch(void* const* d_in, const int* in_sizes, int n_in,
                              void* d_out, int out_size) {
    const float* x     = (const float*)d_in[0];
    const float* cheby = (const float*)d_in[1];   // (8, 9, 4)
    const float* bw    = (const float*)d_in[2];   // (8, 9)
    const float* ss    = (const float*)d_in[3];   // (8, 9)
    float* out = (float*)d_out;

    cudaFuncSetAttribute(kan_conv_kernel,
                         cudaFuncAttributeMaxDynamicSharedMemorySize, SMEM_BYTES);

    const int planes = 16 * 16;                   // B * C
    dim3 grid(planes * (H / TILE_ROWS));          // 4096 blocks
    kan_conv_kernel<<<grid, NTHREADS, SMEM_BYTES>>>(x, cheby, bw, ss, out);
}

// round 13
// speedup vs baseline: 1.1259x; 1.1259x over previous
#include <cuda_runtime.h>

#define H 128
#define W 128
#define NCONV 8
#define TILE_ROWS 8
#define FROWS 10          // TILE_ROWS + 2 halo
#define ESTRIDE 66        // entries per (f,row) in Pe/Po (65/64 used, padded)
#define NTHREADS 256
#define NWARP 8
#define NTASK (FROWS * 5) // 50 feature tasks

// dynamic smem layout (bytes) — weights/bias now in __constant__
#define OFF_PE   0                                   // ull Pe[4][10][66] = 21120  (P[2m])
#define OFF_PO   21120                               // ull Po[4][10][66] = 21120  (P[2m+1])
#define SMEM_BYTES 42240

typedef unsigned long long ull;

__device__ __forceinline__ ull pk2(float lo, float hi) {
    ull r; asm("mov.b64 %0, {%1, %2};" : "=l"(r) : "f"(lo), "f"(hi)); return r;
}
__device__ __forceinline__ void fma2(ull &d, ull a, ull b) {
    asm("fma.rn.f32x2 %0, %1, %2, %0;" : "+l"(d) : "l"(a), "l"(b));
}
__device__ __forceinline__ float tanh_ap(float x) {
    float r; asm("tanh.approx.f32 %0, %1;" : "=f"(r) : "f"(x)); return r;
}

// weights in constant bank: [0..287] dup-pair weights [(tap*4+f)*8+j], [288..295] bias
__constant__ ull cw[296];
__device__   ull g_wstage[296];

// features of one input value: 2 MUFU + a few fma
__device__ __forceinline__ void feats(float xv, float &s, float &t, float &t2, float &t3) {
    t = tanh_ap(xv);                               // tanh
    float th = tanh_ap(0.5f * xv);
    float sg = fmaf(0.5f, th, 0.5f);               // sigmoid(x)
    s  = xv * sg;                                  // silu
    t2 = fmaf(t + t, t, -1.f);                     // T2
    t3 = fmaf(t + t, t2, -t);                      // T3
}

__global__ void prep_kernel(const float* __restrict__ cheby,
                            const float* __restrict__ bw,
                            const float* __restrict__ ss) {
    int idx = threadIdx.x;
    if (idx < 288) {
        int j   = idx & 7;
        int fi  = idx >> 3;
        int tap = fi >> 2;
        int f   = fi & 3;
        float wv;
        if (f == 0) wv = bw[j * 9 + tap];
        else        wv = cheby[(j * 9 + tap) * 4 + f] * ss[j * 9 + tap];
        g_wstage[idx] = pk2(wv, wv);
    } else if (idx < 296) {
        int j = idx - 288;
        float sum = 0.f;
        #pragma unroll
        for (int i = 0; i < 9; i++) sum += cheby[(j * 9 + i) * 4] * ss[j * 9 + i];
        g_wstage[idx] = pk2(sum, sum);
    }
}

__global__ void __launch_bounds__(NTHREADS, 4)
kan_conv_kernel(const float* __restrict__ x, float* __restrict__ out)
{
    extern __shared__ char smem_raw[];
    ull* Pe = (ull*)(smem_raw + OFF_PE);      // P[2m]   = (F(2m),   F(2m+1))
    ull* Po = (ull*)(smem_raw + OFF_PO);      // P[2m+1] = (F(2m+1), F(2m+2))

    const int tid  = threadIdx.x;
    const int wid  = tid >> 5;
    const int lane = tid & 31;
    const int blk  = blockIdx.x;
    const int bc   = blk >> 4;                    // plane b*C + c (0..255)
    const int r0   = (blk & 15) * TILE_ROWS;      // tile top row

    const float* xp = x + (size_t)bc * (H * W);

    // ---- Phase B1: prefetch all feature-input LDGs (MLP up to 7 per warp) ----
    // task = wid + 8q -> (row, chunk c) via increment-only mapping (no divisions).
    float xv[7];
    {
        int row = (wid >= 5) ? 1 : 0;
        int c   = wid - ((wid >= 5) ? 5 : 0);
        #pragma unroll
        for (int q = 0; q < 7; q++) {
            int gr  = r0 - 1 + row;
            int col = ((c << 5) - c) + lane - 1;   // c*31 + lane - 1
            xv[q] = 0.f;
            if ((wid + q * 8 < NTASK) & ((unsigned)gr < H) & ((unsigned)col < W))
                xv[q] = xp[(gr << 7) + col];       // W == 128
            row += 1; c += 3;
            if (c >= 5) { c -= 5; row += 1; }
        }
    }

    // ---- Phase B2: features -> parity-split pair smem, conflict-free ----
    {
        int c    = wid - ((wid >= 5) ? 5 : 0);
        int rowE = (wid >= 5) ? ESTRIDE : 0;       // row * ESTRIDE, incremental
        #pragma unroll
        for (int q = 0; q < 7; q++) {
            if (wid + q * 8 < NTASK) {             // warp-uniform
                int i = ((c << 5) - c) + lane;     // feature index (col = i-1)
                float s, t1, t2, t3;
                feats(xv[q], s, t1, t2, t3);       // x=0 padding -> (0,0,-1,0) ✓
                float ps  = __shfl_up_sync(0xffffffffu, s,  1);
                float pt  = __shfl_up_sync(0xffffffffu, t1, 1);
                float pt2 = __shfl_up_sync(0xffffffffu, t2, 1);
                float pt3 = __shfl_up_sync(0xffffffffu, t3, 1);
                int k = i - 1;
                if (lane >= 1 && k <= 128) {
                    int rb = rowE + (k >> 1);
                    ull v0 = pk2(ps,  s);
                    ull v1 = pk2(pt,  t1);
                    ull v2 = pk2(pt2, t2);
                    ull v3 = pk2(pt3, t3);
                    if ((k & 1) == 0) {
                        Pe[(0 * FROWS) * ESTRIDE + rb] = v0;
                        Pe[(1 * FROWS) * ESTRIDE + rb] = v1;
                        Pe[(2 * FROWS) * ESTRIDE + rb] = v2;
                        Pe[(3 * FROWS) * ESTRIDE + rb] = v3;
                    } else {
                        Po[(0 * FROWS) * ESTRIDE + rb] = v0;
                        Po[(1 * FROWS) * ESTRIDE + rb] = v1;
                        Po[(2 * FROWS) * ESTRIDE + rb] = v2;
                        Po[(3 * FROWS) * ESTRIDE + rb] = v3;
                    }
                }
            }
            c += 3;
            if (c >= 5) { c -= 5; rowE += 2 * ESTRIDE; } else { rowE += ESTRIDE; }
        }
    }
    __syncthreads();

    // ---- Compute: thread -> 2 output rows (ty, ty+1), cols {2L, 2L+1}, 8 j ----
    // Rolling 2-row window; weights read from the constant port (no l1tex traffic).
    const int L  = tid & 63;                       // col-pair index, c0 = 2L
    const int ty = (tid >> 6) * 2;                 // local out rows ty, ty+1

    ull acc[8][2];                                 // [j][r]
    #pragma unroll
    for (int j = 0; j < 8; j++) {
        ull b = cw[288 + j];
        acc[j][0] = b; acc[j][1] = b;
    }

    const int tybase = ty * ESTRIDE + L;           // single IMAD; rest immediates

    #pragma unroll
    for (int f = 0; f < 4; f++) {
        ull lo[3], hi[3];
        {   // input rows ty (lo) and ty+1 (hi)
            int b0 = (f * FROWS) * ESTRIDE + tybase;
            lo[0] = Pe[b0]; lo[1] = Po[b0]; lo[2] = Pe[b0 + 1];
            int b1 = b0 + ESTRIDE;
            hi[0] = Pe[b1]; hi[1] = Po[b1]; hi[2] = Pe[b1 + 1];
        }
        #pragma unroll
        for (int dy = 0; dy < 3; dy++) {
            #pragma unroll
            for (int dx = 0; dx < 3; dx++) {
                const ulonglong2* wp = (const ulonglong2*)&cw[((dy * 3 + dx) * 4 + f) * 8];
                ull f0 = lo[dx];                   // feeds out row ty
                ull f1 = hi[dx];                   // feeds out row ty+1
                {   // j 0..3
                    ulonglong2 w01 = wp[0], w23 = wp[1];
                    fma2(acc[0][0], f0, w01.x); fma2(acc[0][1], f1, w01.x);
                    fma2(acc[1][0], f0, w01.y); fma2(acc[1][1], f1, w01.y);
                    fma2(acc[2][0], f0, w23.x); fma2(acc[2][1], f1, w23.x);
                    fma2(acc[3][0], f0, w23.y); fma2(acc[3][1], f1, w23.y);
                }
                {   // j 4..7
                    ulonglong2 w45 = wp[2], w67 = wp[3];
                    fma2(acc[4][0], f0, w45.x); fma2(acc[4][1], f1, w45.x);
                    fma2(acc[5][0], f0, w45.y); fma2(acc[5][1], f1, w45.y);
                    fma2(acc[6][0], f0, w67.x); fma2(acc[6][1], f1, w67.x);
                    fma2(acc[7][0], f0, w67.y); fma2(acc[7][1], f1, w67.y);
                }
            }
            if (dy < 2) {                          // roll window: lo <- hi, next row
                lo[0] = hi[0]; lo[1] = hi[1]; lo[2] = hi[2];
                int bn = (f * FROWS + dy + 2) * ESTRIDE + tybase;
                hi[0] = Pe[bn]; hi[1] = Po[bn]; hi[2] = Pe[bn + 1];
            }
        }
    }

    // ---- stores: STG.64, dense per warp ----
    float* ob = out + ((size_t)(bc * NCONV) * H + (r0 + ty)) * W + 2 * L;
    #pragma unroll
    for (int j = 0; j < 8; j++) {
        #pragma unroll
        for (int r = 0; r < 2; r++) {
            *(ull*)(ob + (size_t)j * (H * W) + r * W) = acc[j][r];
        }
    }
}

extern "C" void kernel_launch(void* const* d_in, const int* in_sizes, int n_in,
                              void* d_out, int out_size) {
    const float* x     = (const float*)d_in[0];
    const float* cheby = (const float*)d_in[1];   // (8, 9, 4)
    const float* bw    = (const float*)d_in[2];   // (8, 9)
    const float* ss    = (const float*)d_in[3];   // (8, 9)
    float* out = (float*)d_out;

    cudaFuncSetAttribute(kan_conv_kernel,
                         cudaFuncAttributeMaxDynamicSharedMemorySize, SMEM_BYTES);

    // 1) compute dup-pair weights into staging, 2) copy into __constant__ bank
    //    (D2D async memcpy — graph-capturable), 3) main kernel reads via LDC.
    prep_kernel<<<1, 296>>>(cheby, bw, ss);
    void* stage_ptr = nullptr;
    cudaGetSymbolAddress(&stage_ptr, g_wstage);
    cudaMemcpyToSymbolAsync(cw, stage_ptr, 296 * sizeof(ull), 0,
                            cudaMemcpyDeviceToDevice, 0);

    const int planes = 16 * 16;                   // B * C
    dim3 grid(planes * (H / TILE_ROWS));          // 4096 blocks
    kan_conv_kernel<<<grid, NTHREADS, SMEM_BYTES>>>(x, out);
}

// round 14
// speedup vs baseline: 1.1524x; 1.0235x over previous
#include <cuda_runtime.h>

#define H 128
#define W 128
#define NCONV 8
#define TILE_ROWS 8
#define FROWS 10          // TILE_ROWS + 2 halo
#define ESTRIDE 66        // entries per (f,row) in Pe/Po (65/64 used, padded)
#define NTHREADS 256
#define NWARP 8
#define NTASK (FROWS * 5) // 50 feature tasks

// dynamic smem layout (bytes) — weights/bias in __constant__
#define OFF_PE   0                                   // ull Pe[4][10][66] = 21120  (P[2m])
#define OFF_PO   21120                               // ull Po[4][10][66] = 21120  (P[2m+1])
#define SMEM_BYTES 42240

typedef unsigned long long ull;

__device__ __forceinline__ ull pk2(float lo, float hi) {
    ull r; asm("mov.b64 %0, {%1, %2};" : "=l"(r) : "f"(lo), "f"(hi)); return r;
}
__device__ __forceinline__ void fma2(ull &d, ull a, ull b) {
    asm("fma.rn.f32x2 %0, %1, %2, %0;" : "+l"(d) : "l"(a), "l"(b));
}
__device__ __forceinline__ float tanh_ap(float x) {
    float r; asm("tanh.approx.f32 %0, %1;" : "=f"(r) : "f"(x)); return r;
}

// weights in constant bank: [0..287] dup-pair weights [(tap*4+f)*8+j], [288..295] bias
__constant__ ull cw[296];
__device__   ull g_wstage[296];

// features of one input value: 2 MUFU + a few fma
__device__ __forceinline__ void feats(float xv, float &s, float &t, float &t2, float &t3) {
    t = tanh_ap(xv);                               // tanh
    float th = tanh_ap(0.5f * xv);
    float sg = fmaf(0.5f, th, 0.5f);               // sigmoid(x)
    s  = xv * sg;                                  // silu
    t2 = fmaf(t + t, t, -1.f);                     // T2
    t3 = fmaf(t + t, t2, -t);                      // T3
}

__global__ void prep_kernel(const float* __restrict__ cheby,
                            const float* __restrict__ bw,
                            const float* __restrict__ ss) {
    int idx = threadIdx.x;
    if (idx < 288) {
        int j   = idx & 7;
        int fi  = idx >> 3;
        int tap = fi >> 2;
        int f   = fi & 3;
        float wv;
        if (f == 0) wv = bw[j * 9 + tap];
        else        wv = cheby[(j * 9 + tap) * 4 + f] * ss[j * 9 + tap];
        g_wstage[idx] = pk2(wv, wv);
    } else if (idx < 296) {
        int j = idx - 288;
        float sum = 0.f;
        #pragma unroll
        for (int i = 0; i < 9; i++) sum += cheby[(j * 9 + i) * 4] * ss[j * 9 + i];
        g_wstage[idx] = pk2(sum, sum);
    }
}

__global__ void __launch_bounds__(NTHREADS, 5)
kan_conv_kernel(const float* __restrict__ x, float* __restrict__ out)
{
    extern __shared__ char smem_raw[];
    ull* Pe = (ull*)(smem_raw + OFF_PE);      // P[2m]   = (F(2m),   F(2m+1))
    ull* Po = (ull*)(smem_raw + OFF_PO);      // P[2m+1] = (F(2m+1), F(2m+2))

    const int tid  = threadIdx.x;
    const int wid  = tid >> 5;
    const int lane = tid & 31;
    const int blk  = blockIdx.x;
    const int bc   = blk >> 4;                    // plane b*C + c (0..255)
    const int r0   = (blk & 15) * TILE_ROWS;      // tile top row

    const float* xp = x + (size_t)bc * (H * W);

    // ---- Phase B1: prefetch all feature-input LDGs (MLP up to 7 per warp) ----
    // task = wid + 8q -> (row, chunk c) via increment-only mapping (no divisions).
    float xv[7];
    {
        int row = (wid >= 5) ? 1 : 0;
        int c   = wid - ((wid >= 5) ? 5 : 0);
        #pragma unroll
        for (int q = 0; q < 7; q++) {
            int gr  = r0 - 1 + row;
            int col = ((c << 5) - c) + lane - 1;   // c*31 + lane - 1
            xv[q] = 0.f;
            if ((wid + q * 8 < NTASK) & ((unsigned)gr < H) & ((unsigned)col < W))
                xv[q] = xp[(gr << 7) + col];       // W == 128
            row += 1; c += 3;
            if (c >= 5) { c -= 5; row += 1; }
        }
    }

    // ---- Phase B2: features -> parity-split pair smem, conflict-free ----
    {
        int c    = wid - ((wid >= 5) ? 5 : 0);
        int rowE = (wid >= 5) ? ESTRIDE : 0;       // row * ESTRIDE, incremental
        #pragma unroll
        for (int q = 0; q < 7; q++) {
            if (wid + q * 8 < NTASK) {             // warp-uniform
                int i = ((c << 5) - c) + lane;     // feature index (col = i-1)
                float s, t1, t2, t3;
                feats(xv[q], s, t1, t2, t3);       // x=0 padding -> (0,0,-1,0) ✓
                float ps  = __shfl_up_sync(0xffffffffu, s,  1);
                float pt  = __shfl_up_sync(0xffffffffu, t1, 1);
                float pt2 = __shfl_up_sync(0xffffffffu, t2, 1);
                float pt3 = __shfl_up_sync(0xffffffffu, t3, 1);
                int k = i - 1;
                if (lane >= 1 && k <= 128) {
                    int rb = rowE + (k >> 1);
                    ull v0 = pk2(ps,  s);
                    ull v1 = pk2(pt,  t1);
                    ull v2 = pk2(pt2, t2);
                    ull v3 = pk2(pt3, t3);
                    if ((k & 1) == 0) {
                        Pe[(0 * FROWS) * ESTRIDE + rb] = v0;
                        Pe[(1 * FROWS) * ESTRIDE + rb] = v1;
                        Pe[(2 * FROWS) * ESTRIDE + rb] = v2;
                        Pe[(3 * FROWS) * ESTRIDE + rb] = v3;
                    } else {
                        Po[(0 * FROWS) * ESTRIDE + rb] = v0;
                        Po[(1 * FROWS) * ESTRIDE + rb] = v1;
                        Po[(2 * FROWS) * ESTRIDE + rb] = v2;
                        Po[(3 * FROWS) * ESTRIDE + rb] = v3;
                    }
                }
            }
            c += 3;
            if (c >= 5) { c -= 5; rowE += 2 * ESTRIDE; } else { rowE += ESTRIDE; }
        }
    }
    __syncthreads();

    // ---- Compute: thread -> 2 output rows (ty, ty+1), cols {2L, 2L+1}, 8 j ----
    // Rolling 2-row window; weights read from the constant port (no l1tex traffic).
    const int L  = tid & 63;                       // col-pair index, c0 = 2L
    const int ty = (tid >> 6) * 2;                 // local out rows ty, ty+1

    ull acc[8][2];                                 // [j][r]
    #pragma unroll
    for (int j = 0; j < 8; j++) {
        ull b = cw[288 + j];
        acc[j][0] = b; acc[j][1] = b;
    }

    const int tybase = ty * ESTRIDE + L;           // single IMAD; rest immediates

    #pragma unroll
    for (int f = 0; f < 4; f++) {
        ull lo[3], hi[3];
        {   // input rows ty (lo) and ty+1 (hi)
            int b0 = (f * FROWS) * ESTRIDE + tybase;
            lo[0] = Pe[b0]; lo[1] = Po[b0]; lo[2] = Pe[b0 + 1];
            int b1 = b0 + ESTRIDE;
            hi[0] = Pe[b1]; hi[1] = Po[b1]; hi[2] = Pe[b1 + 1];
        }
        #pragma unroll
        for (int dy = 0; dy < 3; dy++) {
            #pragma unroll
            for (int dx = 0; dx < 3; dx++) {
                const ulonglong2* wp = (const ulonglong2*)&cw[((dy * 3 + dx) * 4 + f) * 8];
                ull f0 = lo[dx];                   // feeds out row ty
                ull f1 = hi[dx];                   // feeds out row ty+1
                {   // j 0..3
                    ulonglong2 w01 = wp[0], w23 = wp[1];
                    fma2(acc[0][0], f0, w01.x); fma2(acc[0][1], f1, w01.x);
                    fma2(acc[1][0], f0, w01.y); fma2(acc[1][1], f1, w01.y);
                    fma2(acc[2][0], f0, w23.x); fma2(acc[2][1], f1, w23.x);
                    fma2(acc[3][0], f0, w23.y); fma2(acc[3][1], f1, w23.y);
                }
                {   // j 4..7
                    ulonglong2 w45 = wp[2], w67 = wp[3];
                    fma2(acc[4][0], f0, w45.x); fma2(acc[4][1], f1, w45.x);
                    fma2(acc[5][0], f0, w45.y); fma2(acc[5][1], f1, w45.y);
                    fma2(acc[6][0], f0, w67.x); fma2(acc[6][1], f1, w67.x);
                    fma2(acc[7][0], f0, w67.y); fma2(acc[7][1], f1, w67.y);
                }
            }
            if (dy < 2) {                          // roll window: lo <- hi, next row
                lo[0] = hi[0]; lo[1] = hi[1]; lo[2] = hi[2];
                int bn = (f * FROWS + dy + 2) * ESTRIDE + tybase;
                hi[0] = Pe[bn]; hi[1] = Po[bn]; hi[2] = Pe[bn + 1];
            }
        }
    }

    // ---- stores: STG.64, dense per warp ----
    float* ob = out + ((size_t)(bc * NCONV) * H + (r0 + ty)) * W + 2 * L;
    #pragma unroll
    for (int j = 0; j < 8; j++) {
        #pragma unroll
        for (int r = 0; r < 2; r++) {
            *(ull*)(ob + (size_t)j * (H * W) + r * W) = acc[j][r];
        }
    }
}

extern "C" void kernel_launch(void* const* d_in, const int* in_sizes, int n_in,
                              void* d_out, int out_size) {
    const float* x     = (const float*)d_in[0];
    const float* cheby = (const float*)d_in[1];   // (8, 9, 4)
    const float* bw    = (const float*)d_in[2];   // (8, 9)
    const float* ss    = (const float*)d_in[3];   // (8, 9)
    float* out = (float*)d_out;

    cudaFuncSetAttribute(kan_conv_kernel,
                         cudaFuncAttributeMaxDynamicSharedMemorySize, SMEM_BYTES);

    // 1) compute dup-pair weights into staging, 2) copy into __constant__ bank
    //    (D2D async memcpy — graph-capturable), 3) main kernel reads via LDC.
    prep_kernel<<<1, 296>>>(cheby, bw, ss);
    void* stage_ptr = nullptr;
    cudaGetSymbolAddress(&stage_ptr, g_wstage);
    cudaMemcpyToSymbolAsync(cw, stage_ptr, 296 * sizeof(ull), 0,
                            cudaMemcpyDeviceToDevice, 0);

    const int planes = 16 * 16;                   // B * C
    dim3 grid(planes * (H / TILE_ROWS));          // 4096 blocks
    kan_conv_kernel<<<grid, NTHREADS, SMEM_BYTES>>>(x, out);
}